// round 9
// baseline (speedup 1.0000x reference)
#include <cuda_runtime.h>
#include <cuda_fp16.h>
#include <math.h>
#include <stdint.h>

#define BB 16
#define NN 2048
#define CC 128

// ---------------- device scratch ----------------
__device__ __half g_WsymH[CC * CC];          // 32 KB fp16
__device__ __half g_Hh[BB * NN * CC];        // 8 MB fp16
__device__ float  g_bias[(size_t)NN * NN];   // 16 MB combined mask+diag+A_stat

// ---------------- helpers ----------------
__device__ __forceinline__ uint32_t smem_u32(const void* p) {
    uint32_t a;
    asm("{ .reg .u64 t; cvta.to.shared.u64 t, %1; cvt.u32.u64 %0, t; }" : "=r"(a) : "l"(p));
    return a;
}
__device__ __forceinline__ void cpasync16(uint32_t s, const void* g) {
    asm volatile("cp.async.cg.shared.global [%0], [%1], 16;" :: "r"(s), "l"(g));
}
#define CP_COMMIT() asm volatile("cp.async.commit_group;" ::: "memory")
#define CP_WAIT3()  asm volatile("cp.async.wait_group 3;" ::: "memory")
#define CP_WAIT2()  asm volatile("cp.async.wait_group 2;" ::: "memory")

#define LDSM_X4(r0, r1, r2, r3, addr) \
    asm volatile("ldmatrix.sync.aligned.m8n8.x4.shared.b16 {%0,%1,%2,%3}, [%4];" \
        : "=r"(r0), "=r"(r1), "=r"(r2), "=r"(r3) : "r"(addr))

#define MMA16816(d, a, b0, b1) \
    asm volatile("mma.sync.aligned.m16n8k16.row.col.f32.f16.f16.f32 " \
        "{%0,%1,%2,%3}, {%4,%5,%6,%7}, {%8,%9}, {%0,%1,%2,%3};" \
        : "+f"((d)[0]), "+f"((d)[1]), "+f"((d)[2]), "+f"((d)[3]) \
        : "r"((a)[0]), "r"((a)[1]), "r"((a)[2]), "r"((a)[3]), "r"(b0), "r"(b1))

// ---------------- W_sym ----------------
__global__ void k_wsym(const float* __restrict__ Wq, const float* __restrict__ Wk) {
    int k = blockIdx.x, c = threadIdx.x;
    float a1 = 0.f, a2 = 0.f;
    for (int e = 0; e < CC; e++) {
        a1 += Wq[e * CC + k] * Wk[e * CC + c];
        a2 += Wk[e * CC + k] * Wq[e * CC + c];
    }
    g_WsymH[k * CC + c] = __float2half((0.5f / (sqrtf(128.0f) * 1.5f)) * (a1 + a2));
}

// ---------------- H -> fp16 ----------------
__global__ void k_splitH(const float* __restrict__ H) {
    size_t i = ((size_t)blockIdx.x * blockDim.x + threadIdx.x) * 4;
    float4 v = *(const float4*)(H + i);
    __half2* dst = (__half2*)(g_Hh + i);
    dst[0] = __floats2half2_rn(v.x, v.y);
    dst[1] = __floats2half2_rn(v.z, v.w);
}

// ---------------- combined bias ----------------
__global__ void k_bias(const float* __restrict__ Ast, const float* __restrict__ Mm) {
    size_t idx4 = (size_t)blockIdx.x * blockDim.x + threadIdx.x;
    int n = (int)(idx4 >> 9);
    int mb = (int)(idx4 & 511) * 4;
    float4 a = ((const float4*)Ast)[idx4];
    float4 m = ((const float4*)Mm)[idx4];
    float4 o;
    o.x = (m.x <= 0.f || mb + 0 == n) ? -1e30f : a.x;
    o.y = (m.y <= 0.f || mb + 1 == n) ? -1e30f : a.y;
    o.z = (m.z <= 0.f || mb + 2 == n) ? -1e30f : a.z;
    o.w = (m.w <= 0.f || mb + 3 == n) ? -1e30f : a.w;
    ((float4*)g_bias)[idx4] = o;
}

// ---------------- epilogue piece (one ks-slice of previous tile) ---------
__device__ __forceinline__ void epi_piece(
    int p, int e, int rt, int mo, int no, int q, int qq, int lane, int wn,
    const float (&oa)[4][4][4], float& s1, float& s2,
    float* rowsum, const float* invs, float* __restrict__ out, size_t obase)
{
    int ecol = e & 15;
    int i = p >> 1, jp = p & 1;
    int lrow = mo + i * 16 + q;
    int r1 = rt * 128 + lrow, r2 = r1 + 8;
    int gc0 = ecol * 128 + no;
    if (jp == 0) { s1 = 0.f; s2 = 0.f; }
    bool sum = (e < 16);
    float inv1 = 0.f, inv2 = 0.f;
    if (!sum) { inv1 = invs[lrow]; inv2 = invs[lrow + 8]; }
    #pragma unroll
    for (int jj = 0; jj < 2; jj++) {
        int j = jp * 2 + jj;
        int c = gc0 + j * 8 + qq;
        float2 b1 = __ldcg((const float2*)(g_bias + (size_t)r1 * NN + c));
        float2 b2 = __ldcg((const float2*)(g_bias + (size_t)r2 * NN + c));
        float e0 = __expf(oa[i][j][0] + b1.x);
        float e1 = __expf(oa[i][j][1] + b1.y);
        float e2 = __expf(oa[i][j][2] + b2.x);
        float e3 = __expf(oa[i][j][3] + b2.y);
        if (sum) {
            s1 += e0 + e1; s2 += e2 + e3;
        } else {
            __stcg((float2*)(out + obase + (size_t)r1 * NN + c), make_float2(e0 * inv1, e1 * inv1));
            __stcg((float2*)(out + obase + (size_t)r2 * NN + c), make_float2(e2 * inv2, e3 * inv2));
        }
    }
    if (sum && jp == 1) {
        #pragma unroll
        for (int o = 1; o < 4; o <<= 1) {
            s1 += __shfl_xor_sync(0xffffffffu, s1, o);
            s2 += __shfl_xor_sync(0xffffffffu, s2, o);
        }
        if ((lane & 3) == 0) {
            rowsum[lrow * 4 + wn] += s1;
            rowsum[(lrow + 8) * 4 + wn] += s2;
        }
    }
}

// ---------------- persistent main, epilogue interleaved into GEMM --------
// 1 CTA/SM. smem: bufA 32K | B ring 4x32K | rowsum 2K | invs 512B
// t = 0..15 sum pass, 16..31 write pass; epilogue(t-1) runs inside GEMM(t).
__global__ void __launch_bounds__(256, 1) k_main(float* __restrict__ out) {
    extern __shared__ char smem[];
    uint32_t sm = smem_u32(smem);
    float* rowsum = (float*)(smem + 163840);       // [128][4]
    float* invs   = (float*)(smem + 163840 + 2048);
    int tid = threadIdx.x, wid = tid >> 5, lane = tid & 31;
    int rt = blockIdx.x, b = blockIdx.y;

    ((float2*)rowsum)[tid] = make_float2(0.f, 0.f);

    const __half* Hrt = g_Hh + ((size_t)(b * NN + rt * 128)) * CC;

    // g1: H_rt -> bufA(0), Wsym -> slot3 (131072)
    #pragma unroll
    for (int it = 0; it < 8; it++) {
        int idx = it * 256 + tid;
        int m = idx >> 4, c = idx & 15;
        uint32_t dst = (uint32_t)(m * 256 + ((c ^ (m & 7)) << 4));
        cpasync16(sm + dst, Hrt + (size_t)idx * 8);
        cpasync16(sm + 131072 + dst, g_WsymH + idx * 8);
    }
    CP_COMMIT();
    // g2..g4: B(0..2) -> slots 0..2
    #pragma unroll
    for (int s = 0; s < 3; s++) {
        const __half* Bp = g_Hh + ((size_t)(b * NN + s * 128)) * CC;
        #pragma unroll
        for (int it = 0; it < 8; it++) {
            int idx = it * 256 + tid;
            int m = idx >> 4, c = idx & 15;
            uint32_t dst = (uint32_t)(m * 256 + ((c ^ (m & 7)) << 4));
            cpasync16(sm + 32768u * (s + 1) + dst, Bp + (size_t)idx * 8);
        }
        CP_COMMIT();
    }

    int wm = wid >> 2, wn = wid & 3;          // warp tile 64(m) x 32(n)
    int mo = wm * 64, no = wn * 32;
    int lr = lane & 15, cb = lane >> 4, l7 = lane & 7;
    int q = lane >> 2, qq = (lane & 3) * 2;

    uint32_t rowAoff[4], rowBoff[2];
    #pragma unroll
    for (int i = 0; i < 4; i++) rowAoff[i] = (uint32_t)(mo + i * 16 + lr) * 256u;
    #pragma unroll
    for (int j = 0; j < 2; j++) rowBoff[j] = (uint32_t)(no + j * 16 + lr) * 256u;

    float acc[4][4][4], oldacc[4][4][4];

    // ---- Phase 1: G = H_rt @ Wsym ----
    CP_WAIT3();
    __syncthreads();
    #pragma unroll
    for (int i = 0; i < 4; i++)
        #pragma unroll
        for (int j = 0; j < 4; j++)
            #pragma unroll
            for (int p = 0; p < 4; p++) acc[i][j][p] = 0.f;
    #pragma unroll
    for (int ks = 0; ks < 8; ks++) {
        uint32_t sw = (uint32_t)(((2 * ks + cb) ^ l7) << 4);
        uint32_t a[4][4], bf[2][4];
        #pragma unroll
        for (int i = 0; i < 4; i++)
            LDSM_X4(a[i][0], a[i][1], a[i][2], a[i][3], sm + rowAoff[i] + sw);
        #pragma unroll
        for (int j = 0; j < 2; j++)
            LDSM_X4(bf[j][0], bf[j][1], bf[j][2], bf[j][3], sm + 131072u + rowBoff[j] + sw);
        #pragma unroll
        for (int i = 0; i < 4; i++)
            #pragma unroll
            for (int j = 0; j < 4; j++)
                MMA16816(acc[i][j], a[i], bf[j >> 1][j & 1], bf[j >> 1][2 + (j & 1)]);
    }
    __syncthreads();

    // store G fragments into bufA (fp16, swizzled A layout)
    #pragma unroll
    for (int i = 0; i < 4; i++) {
        int r1 = mo + i * 16 + q;
        #pragma unroll
        for (int j = 0; j < 4; j++) {
            int c = no + j * 8 + qq;
            uint32_t ch = (uint32_t)(c >> 3);
            uint32_t off1 = (uint32_t)r1 * 256u + ((ch ^ ((uint32_t)r1 & 7)) << 4) + (uint32_t)(c & 7) * 2u;
            int r2 = r1 + 8;
            uint32_t off2 = (uint32_t)r2 * 256u + ((ch ^ ((uint32_t)r2 & 7)) << 4) + (uint32_t)(c & 7) * 2u;
            *(__half2*)(smem + off1) = __floats2half2_rn(acc[i][j][0], acc[i][j][1]);
            *(__half2*)(smem + off2) = __floats2half2_rn(acc[i][j][2], acc[i][j][3]);
        }
    }
    // (no commit here; iter-0 sync below covers G-store visibility)

    // ---- main loop: t = 0..32 (t==32 = drain epilogue only) ----
    size_t obase = (size_t)b * NN * NN;
    float s1 = 0.f, s2 = 0.f;

    #pragma unroll 1
    for (int t = 0; t <= 32; t++) {
        if (t < 32) CP_WAIT2();
        __syncthreads();

        if (t == 17) {
            if (tid < 128) {
                float s = rowsum[tid * 4] + rowsum[tid * 4 + 1]
                        + rowsum[tid * 4 + 2] + rowsum[tid * 4 + 3];
                invs[tid] = 1.0f / s;
            }
            __syncthreads();
        }

        if (t < 32) {
            // prefetch B(t+3) into slot (t+3)&3 (freed by GEMM(t-1))
            if (t + 3 < 32) {
                int c2 = (t + 3) & 15;
                uint32_t slot = sm + 32768u * (uint32_t)(((t + 3) & 3) + 1);
                const __half* Bp = g_Hh + ((size_t)(b * NN + c2 * 128)) * CC;
                #pragma unroll
                for (int it = 0; it < 8; it++) {
                    int idx = it * 256 + tid;
                    int m = idx >> 4, c = idx & 15;
                    uint32_t dst = (uint32_t)(m * 256 + ((c ^ (m & 7)) << 4));
                    cpasync16(slot + dst, Bp + (size_t)idx * 8);
                }
            }
            CP_COMMIT();

            uint32_t Bb = sm + 32768u * (uint32_t)((t & 3) + 1);
            #pragma unroll
            for (int i = 0; i < 4; i++)
                #pragma unroll
                for (int j = 0; j < 4; j++)
                    #pragma unroll
                    for (int p = 0; p < 4; p++) acc[i][j][p] = 0.f;

            #pragma unroll
            for (int ks = 0; ks < 8; ks++) {
                uint32_t sw = (uint32_t)(((2 * ks + cb) ^ l7) << 4);
                uint32_t a[4][4], bf[2][4];
                #pragma unroll
                for (int i = 0; i < 4; i++)
                    LDSM_X4(a[i][0], a[i][1], a[i][2], a[i][3], sm + rowAoff[i] + sw);
                #pragma unroll
                for (int j = 0; j < 2; j++)
                    LDSM_X4(bf[j][0], bf[j][1], bf[j][2], bf[j][3], Bb + rowBoff[j] + sw);
                #pragma unroll
                for (int i = 0; i < 4; i++)
                    #pragma unroll
                    for (int j = 0; j < 4; j++)
                        MMA16816(acc[i][j], a[i], bf[j >> 1][j & 1], bf[j >> 1][2 + (j & 1)]);
                // interleaved epilogue piece of previous tile
                if (t > 0)
                    epi_piece(ks, t - 1, rt, mo, no, q, qq, lane, wn,
                              oldacc, s1, s2, rowsum, invs, out, obase);
            }
            // acc -> oldacc
            #pragma unroll
            for (int i = 0; i < 4; i++)
                #pragma unroll
                for (int j = 0; j < 4; j++)
                    #pragma unroll
                    for (int p = 0; p < 4; p++) oldacc[i][j][p] = acc[i][j][p];
        } else {
            // drain: epilogue of tile 31
            #pragma unroll
            for (int p = 0; p < 8; p++)
                epi_piece(p, 31, rt, mo, no, q, qq, lane, wn,
                          oldacc, s1, s2, rowsum, invs, out, obase);
        }
    }
}

// ---------------- launch ----------------
extern "C" void kernel_launch(void* const* d_in, const int* in_sizes, int n_in,
                              void* d_out, int out_size) {
    const float* H   = (const float*)d_in[0];
    const float* Ast = (const float*)d_in[1];
    const float* Mm  = (const float*)d_in[2];
    const float* Wq  = (const float*)d_in[3];
    const float* Wk  = (const float*)d_in[4];
    float* out = (float*)d_out;

    static bool attr_done = false;
    if (!attr_done) {
        cudaFuncSetAttribute(k_main, cudaFuncAttributeMaxDynamicSharedMemorySize, 166400);
        attr_done = true;
    }

    k_wsym<<<CC, CC>>>(Wq, Wk);
    k_splitH<<<(BB * NN * CC / 4) / 256, 256>>>(H);
    k_bias<<<((size_t)NN * NN / 4) / 256, 256>>>(Ast, Mm);
    {
        dim3 grid(NN / 128, BB);   // (rt, b)
        k_main<<<grid, 256, 166400>>>(out);
    }
}

// round 11
// speedup vs baseline: 2.3375x; 2.3375x over previous
#include <cuda_runtime.h>
#include <cuda_fp16.h>
#include <math.h>
#include <stdint.h>

#define BB 16
#define NN 2048
#define CC 128

// ---------------- device scratch ----------------
__device__ __half g_WsymH[CC * CC];           // 32 KB fp16
__device__ __half g_Hh[BB * NN * CC];         // 8 MB fp16
__device__ __half g_biasH[(size_t)NN * NN];   // 8 MB fp16 combined mask+diag+A_stat

// ---------------- helpers ----------------
__device__ __forceinline__ uint32_t smem_u32(const void* p) {
    uint32_t a;
    asm("{ .reg .u64 t; cvta.to.shared.u64 t, %1; cvt.u32.u64 %0, t; }" : "=r"(a) : "l"(p));
    return a;
}
__device__ __forceinline__ void cpasync16(uint32_t s, const void* g) {
    asm volatile("cp.async.cg.shared.global [%0], [%1], 16;" :: "r"(s), "l"(g));
}
#define CP_COMMIT() asm volatile("cp.async.commit_group;" ::: "memory")
#define CP_WAIT1()  asm volatile("cp.async.wait_group 1;" ::: "memory")

#define LDSM_X4(r0, r1, r2, r3, addr) \
    asm volatile("ldmatrix.sync.aligned.m8n8.x4.shared.b16 {%0,%1,%2,%3}, [%4];" \
        : "=r"(r0), "=r"(r1), "=r"(r2), "=r"(r3) : "r"(addr))

#define MMA16816(d, a, b0, b1) \
    asm volatile("mma.sync.aligned.m16n8k16.row.col.f32.f16.f16.f32 " \
        "{%0,%1,%2,%3}, {%4,%5,%6,%7}, {%8,%9}, {%0,%1,%2,%3};" \
        : "+f"((d)[0]), "+f"((d)[1]), "+f"((d)[2]), "+f"((d)[3]) \
        : "r"((a)[0]), "r"((a)[1]), "r"((a)[2]), "r"((a)[3]), "r"(b0), "r"(b1))

// ---------------- W_sym ----------------
__global__ void k_wsym(const float* __restrict__ Wq, const float* __restrict__ Wk) {
    int k = blockIdx.x, c = threadIdx.x;
    float a1 = 0.f, a2 = 0.f;
    for (int e = 0; e < CC; e++) {
        a1 += Wq[e * CC + k] * Wk[e * CC + c];
        a2 += Wk[e * CC + k] * Wq[e * CC + c];
    }
    g_WsymH[k * CC + c] = __float2half((0.5f / (sqrtf(128.0f) * 1.5f)) * (a1 + a2));
}

// ---------------- H -> fp16 ----------------
__global__ void k_splitH(const float* __restrict__ H) {
    size_t i = ((size_t)blockIdx.x * blockDim.x + threadIdx.x) * 4;
    float4 v = *(const float4*)(H + i);
    __half2* dst = (__half2*)(g_Hh + i);
    dst[0] = __floats2half2_rn(v.x, v.y);
    dst[1] = __floats2half2_rn(v.z, v.w);
}

// ---------------- combined bias (fp16): (m==n || M<=0) ? -60000 : A_stat --
__global__ void k_bias(const float* __restrict__ Ast, const float* __restrict__ Mm) {
    size_t idx4 = (size_t)blockIdx.x * blockDim.x + threadIdx.x;
    int n = (int)(idx4 >> 9);
    int mb = (int)(idx4 & 511) * 4;
    float4 a = ((const float4*)Ast)[idx4];
    float4 m = ((const float4*)Mm)[idx4];
    float ox = (m.x <= 0.f || mb + 0 == n) ? -60000.f : a.x;
    float oy = (m.y <= 0.f || mb + 1 == n) ? -60000.f : a.y;
    float oz = (m.z <= 0.f || mb + 2 == n) ? -60000.f : a.z;
    float ow = (m.w <= 0.f || mb + 3 == n) ? -60000.f : a.w;
    __half2* dst = (__half2*)(g_biasH + idx4 * 4);
    dst[0] = __floats2half2_rn(ox, oy);
    dst[1] = __floats2half2_rn(oz, ow);
}

// ---------------- persistent main, two-pass recompute (R6 skeleton) -------
// CTA = (rt, b). smem: bufA 32K | bufB0 32K | bufB1 32K | rowsum 2K | invs 512B
__global__ void __launch_bounds__(256, 2) k_main(float* __restrict__ out) {
    extern __shared__ char smem[];
    uint32_t sm = smem_u32(smem);
    float* rowsum = (float*)(smem + 98304);   // [128][4]
    float* invs   = (float*)(smem + 98304 + 2048);
    int tid = threadIdx.x, wid = tid >> 5, lane = tid & 31;
    int rt = blockIdx.x, b = blockIdx.y;

    ((float2*)rowsum)[tid] = make_float2(0.f, 0.f);

    const __half* Hrt = g_Hh + ((size_t)(b * NN + rt * 128)) * CC;

    // group1: H_rt -> bufA, Wsym -> bufB0
    #pragma unroll
    for (int it = 0; it < 8; it++) {
        int idx = it * 256 + tid;
        int m = idx >> 4, c = idx & 15;
        uint32_t dst = (uint32_t)(m * 256 + ((c ^ (m & 7)) << 4));
        cpasync16(sm + dst, Hrt + (size_t)idx * 8);
        cpasync16(sm + 32768 + dst, g_WsymH + idx * 8);
    }
    CP_COMMIT();
    // group2: ct=0 -> bufB1
    {
        const __half* Bp = g_Hh + (size_t)(b * NN) * CC;
        #pragma unroll
        for (int it = 0; it < 8; it++) {
            int idx = it * 256 + tid;
            int m = idx >> 4, c = idx & 15;
            uint32_t dst = (uint32_t)(m * 256 + ((c ^ (m & 7)) << 4));
            cpasync16(sm + 65536 + dst, Bp + (size_t)idx * 8);
        }
    }
    CP_COMMIT();

    int wm = wid >> 2, wn = wid & 3;          // warp tile 64(m) x 32(n)
    int mo = wm * 64, no = wn * 32;
    int lr = lane & 15, cb = lane >> 4, l7 = lane & 7;
    int q = lane >> 2, qq = (lane & 3) * 2;

    uint32_t rowAoff[4], rowBoff[2];
    #pragma unroll
    for (int i = 0; i < 4; i++) rowAoff[i] = (uint32_t)(mo + i * 16 + lr) * 256u;
    #pragma unroll
    for (int j = 0; j < 2; j++) rowBoff[j] = (uint32_t)(no + j * 16 + lr) * 256u;

    float acc[4][4][4];

    // ---- Phase 1: G tile ----
    CP_WAIT1();
    __syncthreads();
    #pragma unroll
    for (int i = 0; i < 4; i++)
        #pragma unroll
        for (int j = 0; j < 4; j++)
            #pragma unroll
            for (int p = 0; p < 4; p++) acc[i][j][p] = 0.f;
    #pragma unroll
    for (int ks = 0; ks < 8; ks++) {
        uint32_t sw = (uint32_t)(((2 * ks + cb) ^ l7) << 4);
        uint32_t a[4][4], bf[2][4];
        #pragma unroll
        for (int i = 0; i < 4; i++)
            LDSM_X4(a[i][0], a[i][1], a[i][2], a[i][3], sm + rowAoff[i] + sw);
        #pragma unroll
        for (int j = 0; j < 2; j++)
            LDSM_X4(bf[j][0], bf[j][1], bf[j][2], bf[j][3], sm + 32768u + rowBoff[j] + sw);
        #pragma unroll
        for (int i = 0; i < 4; i++)
            #pragma unroll
            for (int j = 0; j < 4; j++)
                MMA16816(acc[i][j], a[i], bf[j >> 1][j & 1], bf[j >> 1][2 + (j & 1)]);
    }
    __syncthreads();

    // store G fragments into bufA (fp16, swizzled A layout)
    #pragma unroll
    for (int i = 0; i < 4; i++) {
        int r1 = mo + i * 16 + q;
        #pragma unroll
        for (int j = 0; j < 4; j++) {
            int c = no + j * 8 + qq;
            uint32_t ch = (uint32_t)(c >> 3);
            uint32_t off1 = (uint32_t)r1 * 256u + ((ch ^ ((uint32_t)r1 & 7)) << 4) + (uint32_t)(c & 7) * 2u;
            int r2 = r1 + 8;
            uint32_t off2 = (uint32_t)r2 * 256u + ((ch ^ ((uint32_t)r2 & 7)) << 4) + (uint32_t)(c & 7) * 2u;
            *(__half2*)(smem + off1) = __floats2half2_rn(acc[i][j][0], acc[i][j][1]);
            *(__half2*)(smem + off2) = __floats2half2_rn(acc[i][j][2], acc[i][j][3]);
        }
    }
    // group3: ct=1 -> bufB0
    {
        const __half* Bp = g_Hh + ((size_t)(b * NN + 128)) * CC;
        #pragma unroll
        for (int it = 0; it < 8; it++) {
            int idx = it * 256 + tid;
            int m = idx >> 4, c = idx & 15;
            uint32_t dst = (uint32_t)(m * 256 + ((c ^ (m & 7)) << 4));
            cpasync16(sm + 32768 + dst, Bp + (size_t)idx * 8);
        }
    }
    CP_COMMIT();
    __syncthreads();   // G stores visible

    // ---- unified 32-iteration loop: t<16 sum pass, t>=16 write pass ----
    size_t obase = (size_t)b * NN * NN;

    #pragma unroll 1
    for (int t = 0; t < 32; t++) {
        int ct = t & 15;
        uint32_t Bb = sm + 32768u + (uint32_t)(((t & 1) ^ 1) << 15);
        CP_WAIT1();
        __syncthreads();

        #pragma unroll
        for (int i = 0; i < 4; i++)
            #pragma unroll
            for (int j = 0; j < 4; j++)
                #pragma unroll
                for (int p = 0; p < 4; p++) acc[i][j][p] = 0.f;
        #pragma unroll
        for (int ks = 0; ks < 8; ks++) {
            uint32_t sw = (uint32_t)(((2 * ks + cb) ^ l7) << 4);
            uint32_t a[4][4], bf[2][4];
            #pragma unroll
            for (int i = 0; i < 4; i++)
                LDSM_X4(a[i][0], a[i][1], a[i][2], a[i][3], sm + rowAoff[i] + sw);
            #pragma unroll
            for (int j = 0; j < 2; j++)
                LDSM_X4(bf[j][0], bf[j][1], bf[j][2], bf[j][3], Bb + rowBoff[j] + sw);
            #pragma unroll
            for (int i = 0; i < 4; i++)
                #pragma unroll
                for (int j = 0; j < 4; j++)
                    MMA16816(acc[i][j], a[i], bf[j >> 1][j & 1], bf[j >> 1][2 + (j & 1)]);
        }
        __syncthreads();   // done reading this B slot

        // prefetch the tile needed at t+2 into the freed slot
        if (t + 2 < 32) {
            int c2 = (t + 2) & 15;
            const __half* Bp = g_Hh + ((size_t)(b * NN + c2 * 128)) * CC;
            #pragma unroll
            for (int it = 0; it < 8; it++) {
                int idx = it * 256 + tid;
                int m = idx >> 4, c = idx & 15;
                uint32_t dst = (uint32_t)(m * 256 + ((c ^ (m & 7)) << 4));
                cpasync16(Bb + dst, Bp + (size_t)idx * 8);
            }
        }
        CP_COMMIT();

        // pass boundary: compute 1/rowsum once
        if (t == 16) {
            if (tid < 128) {
                float s = rowsum[tid * 4] + rowsum[tid * 4 + 1]
                        + rowsum[tid * 4 + 2] + rowsum[tid * 4 + 3];
                invs[tid] = 1.0f / s;
            }
            __syncthreads();
        }

        int gc0 = ct * 128 + no;
        if (t < 16) {
            // ---- sum pass: exp + rowsum, no stores ----
            #pragma unroll
            for (int i = 0; i < 4; i++) {
                int lrow = mo + i * 16 + q;
                int r1 = rt * 128 + lrow, r2 = r1 + 8;
                const __half* b1p = g_biasH + (size_t)r1 * NN;
                const __half* b2p = g_biasH + (size_t)r2 * NN;
                float s1 = 0.f, s2 = 0.f;
                #pragma unroll
                for (int j = 0; j < 4; j++) {
                    int c = gc0 + j * 8 + qq;
                    float2 bb1 = __half22float2(*(const __half2*)(b1p + c));
                    float2 bb2 = __half22float2(*(const __half2*)(b2p + c));
                    s1 += __expf(acc[i][j][0] + bb1.x) + __expf(acc[i][j][1] + bb1.y);
                    s2 += __expf(acc[i][j][2] + bb2.x) + __expf(acc[i][j][3] + bb2.y);
                }
                #pragma unroll
                for (int o = 1; o < 4; o <<= 1) {
                    s1 += __shfl_xor_sync(0xffffffffu, s1, o);
                    s2 += __shfl_xor_sync(0xffffffffu, s2, o);
                }
                if ((lane & 3) == 0) {
                    rowsum[lrow * 4 + wn] += s1;
                    rowsum[(lrow + 8) * 4 + wn] += s2;
                }
            }
        } else {
            // ---- write pass: exp * inv -> normalized store ----
            #pragma unroll
            for (int i = 0; i < 4; i++) {
                int lrow = mo + i * 16 + q;
                int r1 = rt * 128 + lrow, r2 = r1 + 8;
                float inv1 = invs[lrow], inv2 = invs[lrow + 8];
                const __half* b1p = g_biasH + (size_t)r1 * NN;
                const __half* b2p = g_biasH + (size_t)r2 * NN;
                #pragma unroll
                for (int j = 0; j < 4; j++) {
                    int c = gc0 + j * 8 + qq;
                    float2 bb1 = __half22float2(*(const __half2*)(b1p + c));
                    float2 bb2 = __half22float2(*(const __half2*)(b2p + c));
                    float2 e1, e2;
                    e1.x = __expf(acc[i][j][0] + bb1.x) * inv1;
                    e1.y = __expf(acc[i][j][1] + bb1.y) * inv1;
                    e2.x = __expf(acc[i][j][2] + bb2.x) * inv2;
                    e2.y = __expf(acc[i][j][3] + bb2.y) * inv2;
                    *(float2*)(out + obase + (size_t)r1 * NN + c) = e1;
                    *(float2*)(out + obase + (size_t)r2 * NN + c) = e2;
                }
            }
        }
    }
}

// ---------------- launch ----------------
extern "C" void kernel_launch(void* const* d_in, const int* in_sizes, int n_in,
                              void* d_out, int out_size) {
    const float* H   = (const float*)d_in[0];
    const float* Ast = (const float*)d_in[1];
    const float* Mm  = (const float*)d_in[2];
    const float* Wq  = (const float*)d_in[3];
    const float* Wk  = (const float*)d_in[4];
    float* out = (float*)d_out;

    static bool attr_done = false;
    if (!attr_done) {
        cudaFuncSetAttribute(k_main, cudaFuncAttributeMaxDynamicSharedMemorySize, 101376);
        attr_done = true;
    }

    k_wsym<<<CC, CC>>>(Wq, Wk);
    k_splitH<<<(BB * NN * CC / 4) / 256, 256>>>(H);
    k_bias<<<((size_t)NN * NN / 4) / 256, 256>>>(Ast, Mm);
    {
        dim3 grid(NN / 128, BB);   // (rt, b)
        k_main<<<grid, 256, 101376>>>(out);
    }
}

// round 13
// speedup vs baseline: 2.3879x; 1.0216x over previous
#include <cuda_runtime.h>
#include <cuda_fp16.h>
#include <math.h>
#include <stdint.h>

#define BB 16
#define NN 2048
#define CC 128

// ---------------- device scratch ----------------
__device__ __half g_WsymH[CC * CC];            // 32 KB fp16 (pre-scaled by log2e)
__device__ __half g_Hh[BB * NN * CC];          // 8 MB fp16
__device__ __half g_biasH[(size_t)NN * NN];    // 8 MB fp16 (log2-domain)
__device__ __half g_scr[(size_t)BB * NN * NN]; // 134 MB unnormalized exp (fp16)

// ---------------- helpers ----------------
__device__ __forceinline__ uint32_t smem_u32(const void* p) {
    uint32_t a;
    asm("{ .reg .u64 t; cvta.to.shared.u64 t, %1; cvt.u32.u64 %0, t; }" : "=r"(a) : "l"(p));
    return a;
}
__device__ __forceinline__ void cpasync16(uint32_t s, const void* g) {
    asm volatile("cp.async.cg.shared.global [%0], [%1], 16;" :: "r"(s), "l"(g));
}
#define CP_COMMIT() asm volatile("cp.async.commit_group;" ::: "memory")
#define CP_WAIT1()  asm volatile("cp.async.wait_group 1;" ::: "memory")

__device__ __forceinline__ float ex2(float x) {
    float r;
    asm("ex2.approx.ftz.f32 %0, %1;" : "=f"(r) : "f"(x));
    return r;
}
__device__ __forceinline__ float2 h2_to_f2(uint32_t u) {
    __half2 h = *reinterpret_cast<__half2*>(&u);
    return __half22float2(h);
}

#define LDSM_X4(r0, r1, r2, r3, addr) \
    asm volatile("ldmatrix.sync.aligned.m8n8.x4.shared.b16 {%0,%1,%2,%3}, [%4];" \
        : "=r"(r0), "=r"(r1), "=r"(r2), "=r"(r3) : "r"(addr))

#define MMA16816(d, a, b0, b1) \
    asm volatile("mma.sync.aligned.m16n8k16.row.col.f32.f16.f16.f32 " \
        "{%0,%1,%2,%3}, {%4,%5,%6,%7}, {%8,%9}, {%0,%1,%2,%3};" \
        : "+f"((d)[0]), "+f"((d)[1]), "+f"((d)[2]), "+f"((d)[3]) \
        : "r"((a)[0]), "r"((a)[1]), "r"((a)[2]), "r"((a)[3]), "r"(b0), "r"(b1))

// ---------------- W_sym (pre-scaled by log2e) ----------------
__global__ void k_wsym(const float* __restrict__ Wq, const float* __restrict__ Wk) {
    int k = blockIdx.x, c = threadIdx.x;
    float a1 = 0.f, a2 = 0.f;
    for (int e = 0; e < CC; e++) {
        a1 += Wq[e * CC + k] * Wk[e * CC + c];
        a2 += Wk[e * CC + k] * Wq[e * CC + c];
    }
    const float s = (0.5f / (sqrtf(128.0f) * 1.5f)) * 1.4426950408889634f;
    g_WsymH[k * CC + c] = __float2half(s * (a1 + a2));
}

// ---------------- H -> fp16 ----------------
__global__ void k_splitH(const float* __restrict__ H) {
    size_t i = ((size_t)blockIdx.x * blockDim.x + threadIdx.x) * 4;
    float4 v = *(const float4*)(H + i);
    __half2* dst = (__half2*)(g_Hh + i);
    dst[0] = __floats2half2_rn(v.x, v.y);
    dst[1] = __floats2half2_rn(v.z, v.w);
}

// ---------------- combined bias (fp16, log2 domain) ----------------
__global__ void k_bias(const float* __restrict__ Ast, const float* __restrict__ Mm) {
    size_t idx4 = (size_t)blockIdx.x * blockDim.x + threadIdx.x;
    int n = (int)(idx4 >> 9);
    int mb = (int)(idx4 & 511) * 4;
    float4 a = ((const float4*)Ast)[idx4];
    float4 m = ((const float4*)Mm)[idx4];
    const float L2E = 1.4426950408889634f;
    float ox = (m.x <= 0.f || mb + 0 == n) ? -60000.f : a.x * L2E;
    float oy = (m.y <= 0.f || mb + 1 == n) ? -60000.f : a.y * L2E;
    float oz = (m.z <= 0.f || mb + 2 == n) ? -60000.f : a.z * L2E;
    float ow = (m.w <= 0.f || mb + 3 == n) ? -60000.f : a.w * L2E;
    __half2* dst = (__half2*)(g_biasH + idx4 * 4);
    dst[0] = __floats2half2_rn(ox, oy);
    dst[1] = __floats2half2_rn(oz, ow);
}

// ---------------- persistent main: 1 GEMM pass + streaming renorm --------
// CTA = (rt, b). smem: bufA 32K | bufB0 32K | bufB1 32K | rowsum 2K | invs 512B
__global__ void __launch_bounds__(256, 2) k_main(float* __restrict__ out) {
    extern __shared__ char smem[];
    uint32_t sm = smem_u32(smem);
    float* rowsum = (float*)(smem + 98304);   // [128][4]
    float* invs   = (float*)(smem + 98304 + 2048);
    int tid = threadIdx.x, wid = tid >> 5, lane = tid & 31;
    int rt = blockIdx.x, b = blockIdx.y;

    ((float2*)rowsum)[tid] = make_float2(0.f, 0.f);

    const __half* Hrt = g_Hh + ((size_t)(b * NN + rt * 128)) * CC;

    // group1: H_rt -> bufA, Wsym -> bufB0
    #pragma unroll
    for (int it = 0; it < 8; it++) {
        int idx = it * 256 + tid;
        int m = idx >> 4, c = idx & 15;
        uint32_t dst = (uint32_t)(m * 256 + ((c ^ (m & 7)) << 4));
        cpasync16(sm + dst, Hrt + (size_t)idx * 8);
        cpasync16(sm + 32768 + dst, g_WsymH + idx * 8);
    }
    CP_COMMIT();
    // group2: ct=0 -> bufB1
    {
        const __half* Bp = g_Hh + (size_t)(b * NN) * CC;
        #pragma unroll
        for (int it = 0; it < 8; it++) {
            int idx = it * 256 + tid;
            int m = idx >> 4, c = idx & 15;
            uint32_t dst = (uint32_t)(m * 256 + ((c ^ (m & 7)) << 4));
            cpasync16(sm + 65536 + dst, Bp + (size_t)idx * 8);
        }
    }
    CP_COMMIT();

    int wm = wid >> 2, wn = wid & 3;          // warp tile 64(m) x 32(n)
    int mo = wm * 64, no = wn * 32;
    int lr = lane & 15, cb = lane >> 4, l7 = lane & 7;
    int q = lane >> 2, qq = (lane & 3) * 2;

    uint32_t rowAoff[4], rowBoff[2];
    #pragma unroll
    for (int i = 0; i < 4; i++) rowAoff[i] = (uint32_t)(mo + i * 16 + lr) * 256u;
    #pragma unroll
    for (int j = 0; j < 2; j++) rowBoff[j] = (uint32_t)(no + j * 16 + lr) * 256u;

    float acc[4][4][4];

    // ---- Phase 1: G tile (logits pre-scaled by log2e via Wsym) ----
    CP_WAIT1();
    __syncthreads();
    #pragma unroll
    for (int i = 0; i < 4; i++)
        #pragma unroll
        for (int j = 0; j < 4; j++)
            #pragma unroll
            for (int p = 0; p < 4; p++) acc[i][j][p] = 0.f;
    #pragma unroll
    for (int ks = 0; ks < 8; ks++) {
        uint32_t sw = (uint32_t)(((2 * ks + cb) ^ l7) << 4);
        uint32_t a[4][4], bf[2][4];
        #pragma unroll
        for (int i = 0; i < 4; i++)
            LDSM_X4(a[i][0], a[i][1], a[i][2], a[i][3], sm + rowAoff[i] + sw);
        #pragma unroll
        for (int j = 0; j < 2; j++)
            LDSM_X4(bf[j][0], bf[j][1], bf[j][2], bf[j][3], sm + 32768u + rowBoff[j] + sw);
        #pragma unroll
        for (int i = 0; i < 4; i++)
            #pragma unroll
            for (int j = 0; j < 4; j++)
                MMA16816(acc[i][j], a[i], bf[j >> 1][j & 1], bf[j >> 1][2 + (j & 1)]);
    }
    __syncthreads();

    // store G fragments into bufA (fp16, swizzled A layout)
    #pragma unroll
    for (int i = 0; i < 4; i++) {
        int r1 = mo + i * 16 + q;
        #pragma unroll
        for (int j = 0; j < 4; j++) {
            int c = no + j * 8 + qq;
            uint32_t ch = (uint32_t)(c >> 3);
            uint32_t off1 = (uint32_t)r1 * 256u + ((ch ^ ((uint32_t)r1 & 7)) << 4) + (uint32_t)(c & 7) * 2u;
            int r2 = r1 + 8;
            uint32_t off2 = (uint32_t)r2 * 256u + ((ch ^ ((uint32_t)r2 & 7)) << 4) + (uint32_t)(c & 7) * 2u;
            *(__half2*)(smem + off1) = __floats2half2_rn(acc[i][j][0], acc[i][j][1]);
            *(__half2*)(smem + off2) = __floats2half2_rn(acc[i][j][2], acc[i][j][3]);
        }
    }
    // group3: ct=1 -> bufB0
    {
        const __half* Bp = g_Hh + ((size_t)(b * NN + 128)) * CC;
        #pragma unroll
        for (int it = 0; it < 8; it++) {
            int idx = it * 256 + tid;
            int m = idx >> 4, c = idx & 15;
            uint32_t dst = (uint32_t)(m * 256 + ((c ^ (m & 7)) << 4));
            cpasync16(sm + 32768 + dst, Bp + (size_t)idx * 8);
        }
    }
    CP_COMMIT();
    __syncthreads();   // G stores visible

    // ---- single GEMM pass: t = 0..15, store unnormalized exp (fp16) ----
    size_t obase = (size_t)b * NN * NN;

    #pragma unroll 1
    for (int t = 0; t < 16; t++) {
        uint32_t Bb = sm + 32768u + (uint32_t)(((t & 1) ^ 1) << 15);
        CP_WAIT1();
        __syncthreads();

        #pragma unroll
        for (int i = 0; i < 4; i++)
            #pragma unroll
            for (int j = 0; j < 4; j++)
                #pragma unroll
                for (int p = 0; p < 4; p++) acc[i][j][p] = 0.f;
        #pragma unroll
        for (int ks = 0; ks < 8; ks++) {
            uint32_t sw = (uint32_t)(((2 * ks + cb) ^ l7) << 4);
            uint32_t a[4][4], bf[2][4];
            #pragma unroll
            for (int i = 0; i < 4; i++)
                LDSM_X4(a[i][0], a[i][1], a[i][2], a[i][3], sm + rowAoff[i] + sw);
            #pragma unroll
            for (int j = 0; j < 2; j++)
                LDSM_X4(bf[j][0], bf[j][1], bf[j][2], bf[j][3], Bb + rowBoff[j] + sw);
            #pragma unroll
            for (int i = 0; i < 4; i++)
                #pragma unroll
                for (int j = 0; j < 4; j++)
                    MMA16816(acc[i][j], a[i], bf[j >> 1][j & 1], bf[j >> 1][2 + (j & 1)]);
        }
        __syncthreads();   // done reading this B slot

        // prefetch tile t+2
        if (t + 2 < 16) {
            const __half* Bp = g_Hh + ((size_t)(b * NN + (t + 2) * 128)) * CC;
            #pragma unroll
            for (int it = 0; it < 8; it++) {
                int idx = it * 256 + tid;
                int m = idx >> 4, c = idx & 15;
                uint32_t dst = (uint32_t)(m * 256 + ((c ^ (m & 7)) << 4));
                cpasync16(Bb + dst, Bp + (size_t)idx * 8);
            }
        }
        CP_COMMIT();

        // epilogue: exp2(acc + bias) -> fp16 scratch + rowsum
        int gc0 = t * 128 + no;
        #pragma unroll
        for (int i = 0; i < 4; i++) {
            int lrow = mo + i * 16 + q;
            int r1 = rt * 128 + lrow, r2 = r1 + 8;
            const __half* b1p = g_biasH + (size_t)r1 * NN;
            const __half* b2p = g_biasH + (size_t)r2 * NN;
            __half* s1p = g_scr + obase + (size_t)r1 * NN;
            __half* s2p = g_scr + obase + (size_t)r2 * NN;
            float s1 = 0.f, s2 = 0.f;
            #pragma unroll
            for (int j = 0; j < 4; j++) {
                int c = gc0 + j * 8 + qq;
                float2 bb1 = __half22float2(*(const __half2*)(b1p + c));
                float2 bb2 = __half22float2(*(const __half2*)(b2p + c));
                float e0 = ex2(acc[i][j][0] + bb1.x);
                float e1 = ex2(acc[i][j][1] + bb1.y);
                float e2 = ex2(acc[i][j][2] + bb2.x);
                float e3 = ex2(acc[i][j][3] + bb2.y);
                *(__half2*)(s1p + c) = __floats2half2_rn(e0, e1);
                *(__half2*)(s2p + c) = __floats2half2_rn(e2, e3);
                s1 += e0 + e1;
                s2 += e2 + e3;
            }
            #pragma unroll
            for (int o = 1; o < 4; o <<= 1) {
                s1 += __shfl_xor_sync(0xffffffffu, s1, o);
                s2 += __shfl_xor_sync(0xffffffffu, s2, o);
            }
            if ((lane & 3) == 0) {
                rowsum[lrow * 4 + wn] += s1;
                rowsum[(lrow + 8) * 4 + wn] += s2;
            }
        }
    }
    __syncthreads();

    // ---- 1/rowsum ----
    if (tid < 128) {
        float s = rowsum[tid * 4] + rowsum[tid * 4 + 1]
                + rowsum[tid * 4 + 2] + rowsum[tid * 4 + 3];
        invs[tid] = 1.0f / s;
    }
    __syncthreads();

    // ---- streaming renorm: out = inv[row] * scr (fp16 -> fp32) ----
    const uint4* sp4 = (const uint4*)(g_scr + obase + (size_t)(rt * 128) * NN); // 8 halves each
    float4* op4 = (float4*)(out + obase + (size_t)(rt * 128) * NN);
    #pragma unroll 4
    for (int idx = tid; idx < 128 * 256; idx += 256) {   // 256 uint4 per row
        int row = idx >> 8;
        float inv = invs[row];
        uint4 v = sp4[idx];
        float2 f0 = h2_to_f2(v.x), f1 = h2_to_f2(v.y);
        float2 f2 = h2_to_f2(v.z), f3 = h2_to_f2(v.w);
        op4[idx * 2 + 0] = make_float4(f0.x * inv, f0.y * inv, f1.x * inv, f1.y * inv);
        op4[idx * 2 + 1] = make_float4(f2.x * inv, f2.y * inv, f3.x * inv, f3.y * inv);
    }
}

// ---------------- launch ----------------
extern "C" void kernel_launch(void* const* d_in, const int* in_sizes, int n_in,
                              void* d_out, int out_size) {
    const float* H   = (const float*)d_in[0];
    const float* Ast = (const float*)d_in[1];
    const float* Mm  = (const float*)d_in[2];
    const float* Wq  = (const float*)d_in[3];
    const float* Wk  = (const float*)d_in[4];
    float* out = (float*)d_out;

    static bool attr_done = false;
    if (!attr_done) {
        cudaFuncSetAttribute(k_main, cudaFuncAttributeMaxDynamicSharedMemorySize, 101376);
        attr_done = true;
    }

    k_wsym<<<CC, CC>>>(Wq, Wk);
    k_splitH<<<(BB * NN * CC / 4) / 256, 256>>>(H);
    k_bias<<<((size_t)NN * NN / 4) / 256, 256>>>(Ast, Mm);
    {
        dim3 grid(NN / 128, BB);   // (rt, b)
        k_main<<<grid, 256, 101376>>>(out);
    }
}

// round 16
// speedup vs baseline: 2.4226x; 1.0146x over previous
#include <cuda_runtime.h>
#include <cuda_fp16.h>
#include <math.h>
#include <stdint.h>

#define BB 16
#define NN 2048
#define CC 128

// ---------------- device scratch ----------------
__device__ __half g_WsymH[CC * CC];            // 32 KB fp16 (pre-scaled by log2e)
__device__ __half g_Hh[BB * NN * CC];          // 8 MB fp16
__device__ __half g_biasH[(size_t)NN * NN];    // 8 MB fp16 (log2-domain)
__device__ __half g_scr[(size_t)BB * NN * NN]; // 134 MB unnormalized exp (fp16)

// ---------------- helpers ----------------
__device__ __forceinline__ uint32_t smem_u32(const void* p) {
    uint32_t a;
    asm("{ .reg .u64 t; cvta.to.shared.u64 t, %1; cvt.u32.u64 %0, t; }" : "=r"(a) : "l"(p));
    return a;
}
__device__ __forceinline__ void cpasync16(uint32_t s, const void* g) {
    asm volatile("cp.async.cg.shared.global [%0], [%1], 16;" :: "r"(s), "l"(g));
}
#define MBAR_INIT(a, c) \
    asm volatile("mbarrier.init.shared.b64 [%0], %1;" :: "r"(a), "r"(c) : "memory")
#define MBAR_ARRIVE(a) \
    asm volatile("mbarrier.arrive.shared.b64 _, [%0];" :: "r"(a) : "memory")
// .noinc: the cp.async completion CONSUMES one preset arrival (R14 hang fix)
#define CPASYNC_ARRIVE(a) \
    asm volatile("cp.async.mbarrier.arrive.noinc.shared.b64 [%0];" :: "r"(a) : "memory")
__device__ __forceinline__ void mbar_wait(uint32_t a, uint32_t parity) {
    asm volatile(
        "{\n\t.reg .pred P;\n\t"
        "WL_%=:\n\t"
        "mbarrier.try_wait.parity.shared.b64 P, [%0], %1;\n\t"
        "@P bra.uni WD_%=;\n\t"
        "bra.uni WL_%=;\n\t"
        "WD_%=:\n\t}"
        :: "r"(a), "r"(parity) : "memory");
}

__device__ __forceinline__ float ex2(float x) {
    float r;
    asm("ex2.approx.ftz.f32 %0, %1;" : "=f"(r) : "f"(x));
    return r;
}
__device__ __forceinline__ float2 h2_to_f2(uint32_t u) {
    __half2 h = *reinterpret_cast<__half2*>(&u);
    return __half22float2(h);
}

#define LDSM_X4(r0, r1, r2, r3, addr) \
    asm volatile("ldmatrix.sync.aligned.m8n8.x4.shared.b16 {%0,%1,%2,%3}, [%4];" \
        : "=r"(r0), "=r"(r1), "=r"(r2), "=r"(r3) : "r"(addr))

#define MMA16816(d, a, b0, b1) \
    asm volatile("mma.sync.aligned.m16n8k16.row.col.f32.f16.f16.f32 " \
        "{%0,%1,%2,%3}, {%4,%5,%6,%7}, {%8,%9}, {%0,%1,%2,%3};" \
        : "+f"((d)[0]), "+f"((d)[1]), "+f"((d)[2]), "+f"((d)[3]) \
        : "r"((a)[0]), "r"((a)[1]), "r"((a)[2]), "r"((a)[3]), "r"(b0), "r"(b1))

// smem layout
#define SM_S0     32768u
#define SM_S1     65536u
#define SM_ROWSUM 98304u
#define SM_INVS   100352u
#define SM_MBAR   100864u
#define SM_TOTAL  100928

// ---------------- W_sym (pre-scaled by log2e) ----------------
__global__ void k_wsym(const float* __restrict__ Wq, const float* __restrict__ Wk) {
    int k = blockIdx.x, c = threadIdx.x;
    float a1 = 0.f, a2 = 0.f;
    for (int e = 0; e < CC; e++) {
        a1 += Wq[e * CC + k] * Wk[e * CC + c];
        a2 += Wk[e * CC + k] * Wq[e * CC + c];
    }
    const float s = (0.5f / (sqrtf(128.0f) * 1.5f)) * 1.4426950408889634f;
    g_WsymH[k * CC + c] = __float2half(s * (a1 + a2));
}

// ---------------- H -> fp16 ----------------
__global__ void k_splitH(const float* __restrict__ H) {
    size_t i = ((size_t)blockIdx.x * blockDim.x + threadIdx.x) * 4;
    float4 v = *(const float4*)(H + i);
    __half2* dst = (__half2*)(g_Hh + i);
    dst[0] = __floats2half2_rn(v.x, v.y);
    dst[1] = __floats2half2_rn(v.z, v.w);
}

// ---------------- combined bias (fp16, log2 domain) ----------------
__global__ void k_bias(const float* __restrict__ Ast, const float* __restrict__ Mm) {
    size_t idx4 = (size_t)blockIdx.x * blockDim.x + threadIdx.x;
    int n = (int)(idx4 >> 9);
    int mb = (int)(idx4 & 511) * 4;
    float4 a = ((const float4*)Ast)[idx4];
    float4 m = ((const float4*)Mm)[idx4];
    const float L2E = 1.4426950408889634f;
    float ox = (m.x <= 0.f || mb + 0 == n) ? -60000.f : a.x * L2E;
    float oy = (m.y <= 0.f || mb + 1 == n) ? -60000.f : a.y * L2E;
    float oz = (m.z <= 0.f || mb + 2 == n) ? -60000.f : a.z * L2E;
    float ow = (m.w <= 0.f || mb + 3 == n) ? -60000.f : a.w * L2E;
    __half2* dst = (__half2*)(g_biasH + idx4 * 4);
    dst[0] = __floats2half2_rn(ox, oy);
    dst[1] = __floats2half2_rn(oz, ow);
}

// ---------------- persistent main: mbarrier-pipelined GEMM pass ----------
// CTA = (rt, b). smem: bufA 32K | s0 32K | s1 32K | rowsum 2K | invs | mbars
__global__ void __launch_bounds__(256, 2) k_main(float* __restrict__ out) {
    extern __shared__ char smem[];
    uint32_t sm = smem_u32(smem);
    float* rowsum = (float*)(smem + SM_ROWSUM);   // [128][4]
    float* invs   = (float*)(smem + SM_INVS);
    uint32_t mb_fullA = sm + SM_MBAR;
    uint32_t mb_full0 = sm + SM_MBAR + 8;
    uint32_t mb_full1 = sm + SM_MBAR + 16;
    uint32_t mb_free0 = sm + SM_MBAR + 24;
    uint32_t mb_free1 = sm + SM_MBAR + 32;
    int tid = threadIdx.x, wid = tid >> 5, lane = tid & 31;
    int rt = blockIdx.x, b = blockIdx.y;

    if (tid == 0) {
        MBAR_INIT(mb_fullA, 256);
        MBAR_INIT(mb_full0, 256);
        MBAR_INIT(mb_full1, 256);
        MBAR_INIT(mb_free0, 256);
        MBAR_INIT(mb_free1, 256);
    }
    ((float2*)rowsum)[tid] = make_float2(0.f, 0.f);
    __syncthreads();   // mbarrier init visible

    const __half* Hrt = g_Hh + ((size_t)(b * NN + rt * 128)) * CC;

    // prologue issues: A -> bufA, Wsym -> s0 (arrive fullA); B1 -> s1 (arrive full1)
    #pragma unroll
    for (int it = 0; it < 8; it++) {
        int idx = it * 256 + tid;
        int m = idx >> 4, c = idx & 15;
        uint32_t dst = (uint32_t)(m * 256 + ((c ^ (m & 7)) << 4));
        cpasync16(sm + dst, Hrt + (size_t)idx * 8);
        cpasync16(sm + SM_S0 + dst, g_WsymH + idx * 8);
    }
    CPASYNC_ARRIVE(mb_fullA);
    {
        const __half* Bp = g_Hh + ((size_t)(b * NN + 128)) * CC;   // tile 1
        #pragma unroll
        for (int it = 0; it < 8; it++) {
            int idx = it * 256 + tid;
            int m = idx >> 4, c = idx & 15;
            uint32_t dst = (uint32_t)(m * 256 + ((c ^ (m & 7)) << 4));
            cpasync16(sm + SM_S1 + dst, Bp + (size_t)idx * 8);
        }
    }
    CPASYNC_ARRIVE(mb_full1);

    int wm = wid >> 2, wn = wid & 3;          // warp tile 64(m) x 32(n)
    int mo = wm * 64, no = wn * 32;
    int lr = lane & 15, cb = lane >> 4, l7 = lane & 7;
    int q = lane >> 2, qq = (lane & 3) * 2;

    uint32_t rowAoff[4], rowBoff[2];
    #pragma unroll
    for (int i = 0; i < 4; i++) rowAoff[i] = (uint32_t)(mo + i * 16 + lr) * 256u;
    #pragma unroll
    for (int j = 0; j < 2; j++) rowBoff[j] = (uint32_t)(no + j * 16 + lr) * 256u;

    float acc[4][4][4];

    // ---- Phase 1: G = H_rt @ Wsym (A in bufA, Wsym in s0) ----
    mbar_wait(mb_fullA, 0);
    __syncthreads();
    #pragma unroll
    for (int i = 0; i < 4; i++)
        #pragma unroll
        for (int j = 0; j < 4; j++)
            #pragma unroll
            for (int p = 0; p < 4; p++) acc[i][j][p] = 0.f;
    #pragma unroll
    for (int ks = 0; ks < 8; ks++) {
        uint32_t sw = (uint32_t)(((2 * ks + cb) ^ l7) << 4);
        uint32_t a[4][4], bf[2][4];
        #pragma unroll
        for (int i = 0; i < 4; i++)
            LDSM_X4(a[i][0], a[i][1], a[i][2], a[i][3], sm + rowAoff[i] + sw);
        #pragma unroll
        for (int j = 0; j < 2; j++)
            LDSM_X4(bf[j][0], bf[j][1], bf[j][2], bf[j][3], sm + SM_S0 + rowBoff[j] + sw);
        #pragma unroll
        for (int i = 0; i < 4; i++)
            #pragma unroll
            for (int j = 0; j < 4; j++)
                MMA16816(acc[i][j], a[i], bf[j >> 1][j & 1], bf[j >> 1][2 + (j & 1)]);
    }
    __syncthreads();   // all reads of bufA/s0 done

    // store G fragments into bufA (fp16, swizzled A layout)
    #pragma unroll
    for (int i = 0; i < 4; i++) {
        int r1 = mo + i * 16 + q;
        #pragma unroll
        for (int j = 0; j < 4; j++) {
            int c = no + j * 8 + qq;
            uint32_t ch = (uint32_t)(c >> 3);
            uint32_t off1 = (uint32_t)r1 * 256u + ((ch ^ ((uint32_t)r1 & 7)) << 4) + (uint32_t)(c & 7) * 2u;
            int r2 = r1 + 8;
            uint32_t off2 = (uint32_t)r2 * 256u + ((ch ^ ((uint32_t)r2 & 7)) << 4) + (uint32_t)(c & 7) * 2u;
            *(__half2*)(smem + off1) = __floats2half2_rn(acc[i][j][0], acc[i][j][1]);
            *(__half2*)(smem + off2) = __floats2half2_rn(acc[i][j][2], acc[i][j][3]);
        }
    }
    // B0 -> s0 (Wsym dead after the sync above)
    {
        const __half* Bp = g_Hh + (size_t)(b * NN) * CC;   // tile 0
        #pragma unroll
        for (int it = 0; it < 8; it++) {
            int idx = it * 256 + tid;
            int m = idx >> 4, c = idx & 15;
            uint32_t dst = (uint32_t)(m * 256 + ((c ^ (m & 7)) << 4));
            cpasync16(sm + SM_S0 + dst, Bp + (size_t)idx * 8);
        }
    }
    CPASYNC_ARRIVE(mb_full0);
    __syncthreads();   // G stores visible to all warps

    // ---- pipelined GEMM pass: t = 0..15 ----
    size_t obase = (size_t)b * NN * NN;

    #pragma unroll 1
    for (int t = 0; t < 16; t++) {
        uint32_t slot = sm + SM_S0 + (uint32_t)((t & 1) << 15);
        uint32_t mb_full = (t & 1) ? mb_full1 : mb_full0;
        uint32_t mb_free = (t & 1) ? mb_free1 : mb_free0;
        uint32_t parity = (uint32_t)((t >> 1) & 1);

        mbar_wait(mb_full, parity);   // B(t) resident

        #pragma unroll
        for (int i = 0; i < 4; i++)
            #pragma unroll
            for (int j = 0; j < 4; j++)
                #pragma unroll
                for (int p = 0; p < 4; p++) acc[i][j][p] = 0.f;
        #pragma unroll
        for (int ks = 0; ks < 8; ks++) {
            uint32_t sw = (uint32_t)(((2 * ks + cb) ^ l7) << 4);
            uint32_t a[4][4], bf[2][4];
            #pragma unroll
            for (int i = 0; i < 4; i++)
                LDSM_X4(a[i][0], a[i][1], a[i][2], a[i][3], sm + rowAoff[i] + sw);
            #pragma unroll
            for (int j = 0; j < 2; j++)
                LDSM_X4(bf[j][0], bf[j][1], bf[j][2], bf[j][3], slot + rowBoff[j] + sw);
            #pragma unroll
            for (int i = 0; i < 4; i++)
                #pragma unroll
                for (int j = 0; j < 4; j++)
                    MMA16816(acc[i][j], a[i], bf[j >> 1][j & 1], bf[j >> 1][2 + (j & 1)]);
        }
        MBAR_ARRIVE(mb_free);   // this thread done reading slot

        // prefetch B(t+2) into the same slot once ALL threads have read it
        if (t < 14) {
            mbar_wait(mb_free, parity);
            const __half* Bp = g_Hh + ((size_t)(b * NN + (t + 2) * 128)) * CC;
            #pragma unroll
            for (int it = 0; it < 8; it++) {
                int idx = it * 256 + tid;
                int m = idx >> 4, c = idx & 15;
                uint32_t dst = (uint32_t)(m * 256 + ((c ^ (m & 7)) << 4));
                cpasync16(slot + dst, Bp + (size_t)idx * 8);
            }
            CPASYNC_ARRIVE(mb_full);
        }

        // epilogue: exp2(acc + bias) -> fp16 scratch + rowsum
        int gc0 = t * 128 + no;
        #pragma unroll
        for (int i = 0; i < 4; i++) {
            int lrow = mo + i * 16 + q;
            int r1 = rt * 128 + lrow, r2 = r1 + 8;
            const __half* b1p = g_biasH + (size_t)r1 * NN;
            const __half* b2p = g_biasH + (size_t)r2 * NN;
            __half* s1p = g_scr + obase + (size_t)r1 * NN;
            __half* s2p = g_scr + obase + (size_t)r2 * NN;
            float s1 = 0.f, s2 = 0.f;
            #pragma unroll
            for (int j = 0; j < 4; j++) {
                int c = gc0 + j * 8 + qq;
                float2 bb1 = __half22float2(*(const __half2*)(b1p + c));
                float2 bb2 = __half22float2(*(const __half2*)(b2p + c));
                float e0 = ex2(acc[i][j][0] + bb1.x);
                float e1 = ex2(acc[i][j][1] + bb1.y);
                float e2 = ex2(acc[i][j][2] + bb2.x);
                float e3 = ex2(acc[i][j][3] + bb2.y);
                *(__half2*)(s1p + c) = __floats2half2_rn(e0, e1);
                *(__half2*)(s2p + c) = __floats2half2_rn(e2, e3);
                s1 += e0 + e1;
                s2 += e2 + e3;
            }
            #pragma unroll
            for (int o = 1; o < 4; o <<= 1) {
                s1 += __shfl_xor_sync(0xffffffffu, s1, o);
                s2 += __shfl_xor_sync(0xffffffffu, s2, o);
            }
            if ((lane & 3) == 0) {
                rowsum[lrow * 4 + wn] += s1;
                rowsum[(lrow + 8) * 4 + wn] += s2;
            }
        }
    }
    __syncthreads();

    // ---- 1/rowsum ----
    if (tid < 128) {
        float s = rowsum[tid * 4] + rowsum[tid * 4 + 1]
                + rowsum[tid * 4 + 2] + rowsum[tid * 4 + 3];
        invs[tid] = 1.0f / s;
    }
    __syncthreads();

    // ---- streaming renorm: out = inv[row] * scr (fp16 -> fp32) ----
    const uint4* sp4 = (const uint4*)(g_scr + obase + (size_t)(rt * 128) * NN);
    float4* op4 = (float4*)(out + obase + (size_t)(rt * 128) * NN);
    #pragma unroll 4
    for (int idx = tid; idx < 128 * 256; idx += 256) {
        int row = idx >> 8;
        float inv = invs[row];
        uint4 v = sp4[idx];
        float2 f0 = h2_to_f2(v.x), f1 = h2_to_f2(v.y);
        float2 f2 = h2_to_f2(v.z), f3 = h2_to_f2(v.w);
        __stcg(op4 + idx * 2 + 0, make_float4(f0.x * inv, f0.y * inv, f1.x * inv, f1.y * inv));
        __stcg(op4 + idx * 2 + 1, make_float4(f2.x * inv, f2.y * inv, f3.x * inv, f3.y * inv));
    }
}

// ---------------- launch ----------------
extern "C" void kernel_launch(void* const* d_in, const int* in_sizes, int n_in,
                              void* d_out, int out_size) {
    const float* H   = (const float*)d_in[0];
    const float* Ast = (const float*)d_in[1];
    const float* Mm  = (const float*)d_in[2];
    const float* Wq  = (const float*)d_in[3];
    const float* Wk  = (const float*)d_in[4];
    float* out = (float*)d_out;

    static bool attr_done = false;
    if (!attr_done) {
        cudaFuncSetAttribute(k_main, cudaFuncAttributeMaxDynamicSharedMemorySize, SM_TOTAL);
        attr_done = true;
    }

    k_wsym<<<CC, CC>>>(Wq, Wk);
    k_splitH<<<(BB * NN * CC / 4) / 256, 256>>>(H);
    k_bias<<<((size_t)NN * NN / 4) / 256, 256>>>(Ast, Mm);
    {
        dim3 grid(NN / 128, BB);   // (rt, b)
        k_main<<<grid, 256, SM_TOTAL>>>(out);
    }
}